// round 10
// baseline (speedup 1.0000x reference)
#include <cuda_runtime.h>
#include <cuda_fp16.h>
#include <cstdint>

#define T_STEPS 300
#define BATCH   256
#define NIN     128
#define NH      512
#define NOUT    3
#define DTSEC   0.01f
#define ALPHA_N 0.2f

#define Y_SIZE (BATCH * T_STEPS * NOUT)

// tile geometry for the DSMEM exchange
#define ROW_H   72                  // halves per padded row (64 data + 8 pad)
#define TILE_H  (16 * ROW_H)        // halves per slice tile = 1152
#define TILE_B  (TILE_H * 2)        // bytes per slice tile  = 2304
#define RP_BUF_H (8 * TILE_H)       // halves per rp buffer  = 9216
#define EXP_TX  (8 * TILE_B)        // 18432 bytes per step

// ---------------- device scratch (static, allocation-free) ----------------
__device__ float     g_drive[(size_t)T_STEPS * BATCH * NH];   // 157 MB
__device__ uint32_t  g_wrnnp[(NH / 2) * NH];                  // packed half2 (k-pair x h)
__device__ uint32_t  g_winp[(NIN / 2) * NH];
__device__ float     g_wout[NH * NOUT];
__device__ float     g_yraw[(size_t)T_STEPS * BATCH * NOUT];

__device__ __forceinline__ uint32_t smem_u32(const void* p) {
    uint32_t a;
    asm("{ .reg .u64 t; cvta.to.shared.u64 t, %1; cvt.u32.u64 %0, t; }" : "=r"(a) : "l"(p));
    return a;
}

// ---------------- prep -----------------------------------------------------
__global__ void prep_kernel(const float* __restrict__ w_in, const float* __restrict__ w_in_mask,
                            const float* __restrict__ w_rnn_base, const float* __restrict__ conn,
                            const float* __restrict__ ei, const float* __restrict__ w_out,
                            const float* __restrict__ w_out_mask)
{
    int tid = blockIdx.x * blockDim.x + threadIdx.x;
    int nth = gridDim.x * blockDim.x;

    for (int i = tid; i < (NH / 2) * NH; i += nth) {
        int p = i >> 9, h = i & (NH - 1);
        int k0 = 2 * p, k1 = 2 * p + 1;
        float s0 = ei[k0 * NH + k0];
        float s1 = ei[k1 * NH + k1];
        float v0 = fmaxf(w_rnn_base[k0 * NH + h] * conn[k0 * NH + h], 0.f) * s0;
        float v1 = fmaxf(w_rnn_base[k1 * NH + h] * conn[k1 * NH + h], 0.f) * s1;
        __half2 hv = __floats2half2_rn(v0, v1);
        g_wrnnp[i] = *reinterpret_cast<uint32_t*>(&hv);
    }
    for (int i = tid; i < (NIN / 2) * NH; i += nth) {
        int p = i >> 9, h = i & (NH - 1);
        float v0 = w_in[(2 * p) * NH + h] * w_in_mask[(2 * p) * NH + h];
        float v1 = w_in[(2 * p + 1) * NH + h] * w_in_mask[(2 * p + 1) * NH + h];
        __half2 hv = __floats2half2_rn(v0, v1);
        g_winp[i] = *reinterpret_cast<uint32_t*>(&hv);
    }
    for (int i = tid; i < NH * NOUT; i += nth)
        g_wout[i] = fmaxf(w_out[i] * w_out_mask[i], 0.f);
}

// ---------------- drive GEMM: drive = 0.2*(inp@w_in_eff + b_rnn) + noise ---
__global__ void __launch_bounds__(256) drive_gemm(const float* __restrict__ inp,
                                                  const float* __restrict__ noise,
                                                  const float* __restrict__ b_rnn)
{
    __shared__ __half   a_s[64 * 136];
    __shared__ uint32_t b_s[64 * 68];

    int row0 = blockIdx.x * 64;
    int n0   = blockIdx.y * 64;
    int tid  = threadIdx.x;

    #pragma unroll
    for (int j = 0; j < 32; j++) {
        int idx = tid + j * 256;
        int i = idx >> 7, k = idx & 127;
        a_s[i * 136 + k] = __float2half_rn(inp[(size_t)(row0 + i) * NIN + k]);
    }
    #pragma unroll
    for (int j = 0; j < 16; j++) {
        int idx = tid + j * 256;
        int p = idx >> 6, c = idx & 63;
        b_s[p * 68 + c] = g_winp[p * NH + n0 + c];
    }
    __syncthreads();

    int w = tid >> 5, lane = tid & 31;
    int g = lane >> 2, t = lane & 3;
    int m0 = (w & 3) * 16;
    int nw = (w >> 2) * 32;

    float acc[4][4] = {};
    #pragma unroll
    for (int kk = 0; kk < 8; kk++) {
        int k0 = kk * 16;
        uint32_t a0 = *reinterpret_cast<const uint32_t*>(&a_s[(m0 + g) * 136 + k0 + 2 * t]);
        uint32_t a1 = *reinterpret_cast<const uint32_t*>(&a_s[(m0 + g + 8) * 136 + k0 + 2 * t]);
        uint32_t a2 = *reinterpret_cast<const uint32_t*>(&a_s[(m0 + g) * 136 + k0 + 8 + 2 * t]);
        uint32_t a3 = *reinterpret_cast<const uint32_t*>(&a_s[(m0 + g + 8) * 136 + k0 + 8 + 2 * t]);
        #pragma unroll
        for (int s = 0; s < 4; s++) {
            int col = nw + 8 * s + g;
            uint32_t b0 = b_s[(kk * 8 + t) * 68 + col];
            uint32_t b1 = b_s[(kk * 8 + t + 4) * 68 + col];
            asm volatile("mma.sync.aligned.m16n8k16.row.col.f32.f16.f16.f32 "
                         "{%0,%1,%2,%3}, {%4,%5,%6,%7}, {%8,%9}, {%0,%1,%2,%3};"
                         : "+f"(acc[s][0]), "+f"(acc[s][1]), "+f"(acc[s][2]), "+f"(acc[s][3])
                         : "r"(a0), "r"(a1), "r"(a2), "r"(a3), "r"(b0), "r"(b1));
        }
    }

    #pragma unroll
    for (int s = 0; s < 4; s++) {
        int gc  = n0 + nw + 8 * s + 2 * t;
        float br0 = b_rnn[gc], br1 = b_rnn[gc + 1];
        int r0 = row0 + m0 + g;
        int r1 = r0 + 8;
        float2 nz0 = *reinterpret_cast<const float2*>(&noise[(size_t)r0 * NH + gc]);
        float2 nz1 = *reinterpret_cast<const float2*>(&noise[(size_t)r1 * NH + gc]);
        float2 d0, d1;
        d0.x = ALPHA_N * (acc[s][0] + br0) + nz0.x;
        d0.y = ALPHA_N * (acc[s][1] + br1) + nz0.y;
        d1.x = ALPHA_N * (acc[s][2] + br0) + nz1.x;
        d1.y = ALPHA_N * (acc[s][3] + br1) + nz1.y;
        *reinterpret_cast<float2*>(&g_drive[(size_t)r0 * NH + gc]) = d0;
        *reinterpret_cast<float2*>(&g_drive[(size_t)r1 * NH + gc]) = d1;
    }
}

// ---------------- persistent step kernel -----------------------------------
// 128 CTAs = 16 clusters of 8 (one cluster per 16-row batch group).
// Exchange: each producer bulk-copies its 2304B tile into all 8 cluster CTAs'
// smem via cp.async.bulk.shared::cluster (engine-driven, completes on the
// DESTINATION mbarrier). Consumers expect_tx + parity-wait; no polling, no
// L2 pull. Two mbarriers (one per buffer) make <=1-step producer skew safe.
__global__ void __launch_bounds__(256, 1) __cluster_dims__(8, 1, 1) step_kernel(
    const float* __restrict__ x_init, const float* __restrict__ sx_init,
    const float* __restrict__ su_init,
    const float* __restrict__ a_std, const float* __restrict__ a_stf,
    const float* __restrict__ Uv, const float* __restrict__ dynv,
    float* __restrict__ out_x)
{
    __shared__ __align__(16) __half rp[2 * RP_BUF_H];   // [buf][slice][16][72]
    __shared__ __align__(16) __half srcb[2 * TILE_H];   // [buf][16][72]
    __shared__ __align__(8)  uint64_t mbars[2];

    int cta   = blockIdx.x;
    int grp   = cta >> 3;
    int slice = cta & 7;
    int b0 = grp * 16;
    int h0 = slice * 64;
    int tid = threadIdx.x;
    int w = tid >> 5, lane = tid & 31;
    int g = lane >> 2, t = lane & 3;

    uint32_t mb_addr0 = smem_u32(&mbars[0]);
    uint32_t mb_addr1 = smem_u32(&mbars[1]);
    if (tid == 0) {
        asm volatile("mbarrier.init.shared.b64 [%0], 1;" :: "r"(mb_addr0) : "memory");
        asm volatile("mbarrier.init.shared.b64 [%0], 1;" :: "r"(mb_addr1) : "memory");
    }

    // ---- persistent B fragments for W_rnn slice (registers, step-invariant)
    uint32_t breg0[32], breg1[32];
    {
        int c = h0 + 8 * w + g;
        #pragma unroll
        for (int kk = 0; kk < 32; kk++) {
            breg0[kk] = g_wrnnp[(size_t)(kk * 8 + t) * NH + c];
            breg1[kk] = g_wrnnp[(size_t)(kk * 8 + t + 4) * NH + c];
        }
    }

    int hb  = h0 + 8 * w + 2 * t;
    int br0 = b0 + g, br1 = b0 + g + 8;

    float as0 = a_std[hb], as1 = a_std[hb + 1];
    float af0 = a_stf[hb], af1 = a_stf[hb + 1];
    float U0  = Uv[hb],    U1  = Uv[hb + 1];
    float dy0 = dynv[hb],  dy1 = dynv[hb + 1];

    float x0 = x_init[br0 * NH + hb],   x1 = x_init[br0 * NH + hb + 1];
    float x2 = x_init[br1 * NH + hb],   x3 = x_init[br1 * NH + hb + 1];
    float sx0 = sx_init[br0 * NH + hb], sx1 = sx_init[br0 * NH + hb + 1];
    float sx2 = sx_init[br1 * NH + hb], sx3 = sx_init[br1 * NH + hb + 1];
    float su0 = su_init[br0 * NH + hb], su1 = su_init[br0 * NH + hb + 1];
    float su2 = su_init[br1 * NH + hb], su3 = su_init[br1 * NH + hb + 1];

    // ldmatrix lane base: row (lane&15), 16B half-select for lanes 16-31.
    // rp row stride 144B -> 16B-aligned, conflict-free (bank = 4r + const).
    uint32_t lds_base = smem_u32(rp) + (lane & 15) * 144 + ((lane >> 4) & 1) * 16;
    uint32_t rp_u32   = smem_u32(rp);
    uint32_t src_u32  = smem_u32(srcb);

    // producer staging offsets (halves): rows g, g+8, local col 8w+2t
    __half2* st0 = reinterpret_cast<__half2*>(srcb + g * ROW_H + 8 * w + 2 * t);
    __half2* st1 = reinterpret_cast<__half2*>(srcb + (g + 8) * ROW_H + 8 * w + 2 * t);

    // cluster sync: all peers' mbarriers initialized before any bulk copy
    asm volatile("barrier.cluster.arrive.aligned;" ::: "memory");
    asm volatile("barrier.cluster.wait.aligned;"   ::: "memory");

    for (int ts = 0; ts < T_STEPS; ts++) {
        int buf = ts & 1;
        uint32_t mb_local = buf ? mb_addr1 : mb_addr0;

        // ---- post expected bytes for this step's 8 incoming tiles ----
        if (tid == 0)
            asm volatile("mbarrier.arrive.expect_tx.shared.b64 _, [%0], %1;"
                         :: "r"(mb_local), "r"((uint32_t)EXP_TX) : "memory");

        // ---- prefetch drive early (consumed after MMA) ----
        float2 d0 = *reinterpret_cast<const float2*>(&g_drive[((size_t)ts * BATCH + br0) * NH + hb]);
        float2 d1 = *reinterpret_cast<const float2*>(&g_drive[((size_t)ts * BATCH + br1) * NH + hb]);

        // ---- phase 1: STP update + x_post ----
        float xp0, xp1, xp2, xp3;
        {
            float r, sxn, sun;
            r = fmaxf(x0, 0.f);
            sxn = sx0 + (as0 * (1.f - sx0) - DTSEC * su0 * sx0 * r) * dy0;
            sun = su0 + (af0 * (U0 - su0) + DTSEC * U0 * (1.f - su0) * r) * dy0;
            sx0 = fminf(fmaxf(sxn, 0.f), 1.f); su0 = fminf(fmaxf(sun, 0.f), 1.f);
            xp0 = su0 * sx0 * x0;

            r = fmaxf(x1, 0.f);
            sxn = sx1 + (as1 * (1.f - sx1) - DTSEC * su1 * sx1 * r) * dy1;
            sun = su1 + (af1 * (U1 - su1) + DTSEC * U1 * (1.f - su1) * r) * dy1;
            sx1 = fminf(fmaxf(sxn, 0.f), 1.f); su1 = fminf(fmaxf(sun, 0.f), 1.f);
            xp1 = su1 * sx1 * x1;

            r = fmaxf(x2, 0.f);
            sxn = sx2 + (as0 * (1.f - sx2) - DTSEC * su2 * sx2 * r) * dy0;
            sun = su2 + (af0 * (U0 - su2) + DTSEC * U0 * (1.f - su2) * r) * dy0;
            sx2 = fminf(fmaxf(sxn, 0.f), 1.f); su2 = fminf(fmaxf(sun, 0.f), 1.f);
            xp2 = su2 * sx2 * x2;

            r = fmaxf(x3, 0.f);
            sxn = sx3 + (as1 * (1.f - sx3) - DTSEC * su3 * sx3 * r) * dy1;
            sun = su3 + (af1 * (U1 - su3) + DTSEC * U1 * (1.f - su3) * r) * dy1;
            sx3 = fminf(fmaxf(sxn, 0.f), 1.f); su3 = fminf(fmaxf(sun, 0.f), 1.f);
            xp3 = su3 * sx3 * x3;
        }

        // ---- stage own tile into local src buffer (fp16, padded rows) ----
        st0[buf * (TILE_H / 2)] = __floats2half2_rn(fmaxf(xp0, 0.f), fmaxf(xp1, 0.f));
        st1[buf * (TILE_H / 2)] = __floats2half2_rn(fmaxf(xp2, 0.f), fmaxf(xp3, 0.f));
        __syncthreads();   // all stores done; also guards rp reuse per induction

        // ---- push: 8 engine-driven bulk copies, one per cluster rank ----
        if (tid < 8) {
            asm volatile("fence.proxy.async.shared::cta;" ::: "memory");
            uint32_t dst_local = rp_u32 + (uint32_t)(buf * 8 + slice) * TILE_B;
            uint32_t src_addr  = src_u32 + (uint32_t)buf * TILE_B;
            uint32_t dst_rem, mb_rem;
            asm volatile("mapa.shared::cluster.u32 %0, %1, %2;"
                         : "=r"(dst_rem) : "r"(dst_local), "r"(tid));
            asm volatile("mapa.shared::cluster.u32 %0, %1, %2;"
                         : "=r"(mb_rem) : "r"(mb_local), "r"(tid));
            asm volatile("cp.async.bulk.shared::cluster.shared::cta.mbarrier::complete_tx::bytes "
                         "[%0], [%1], %2, [%3];"
                         :: "r"(dst_rem), "r"(src_addr), "r"((uint32_t)TILE_B), "r"(mb_rem)
                         : "memory");
        }

        // ---- wait: HW-sleep until all 8 tiles landed in our smem ----
        {
            uint32_t parity = (ts >> 1) & 1;
            uint32_t done = 0;
            while (!done)
                asm volatile("{ .reg .pred p; "
                             "mbarrier.try_wait.parity.acquire.cta.shared::cta.b64 p, [%1], %2, 0x989680; "
                             "selp.b32 %0, 1, 0, p; }"
                             : "=r"(done) : "r"(mb_local), "r"(parity) : "memory");
        }

        // ---- mma: C[16x64] = rpost[16x512] @ W[512x64]; 4 accumulator chains
        uint32_t lds_a = lds_base + (uint32_t)buf * (RP_BUF_H * 2);
        float acc[4][4] = {};
        #pragma unroll
        for (int kk = 0; kk < 32; kk++) {
            uint32_t a0, a1, a2, a3;
            asm volatile("ldmatrix.sync.aligned.m8n8.x4.shared.b16 {%0,%1,%2,%3}, [%4];"
                         : "=r"(a0), "=r"(a1), "=r"(a2), "=r"(a3)
                         : "r"(lds_a + (kk >> 2) * TILE_B + (kk & 3) * 32));
            float* A = acc[kk & 3];
            asm volatile("mma.sync.aligned.m16n8k16.row.col.f32.f16.f16.f32 "
                         "{%0,%1,%2,%3}, {%4,%5,%6,%7}, {%8,%9}, {%0,%1,%2,%3};"
                         : "+f"(A[0]), "+f"(A[1]), "+f"(A[2]), "+f"(A[3])
                         : "r"(a0), "r"(a1), "r"(a2), "r"(a3), "r"(breg0[kk]), "r"(breg1[kk]));
        }
        float s0 = (acc[0][0] + acc[1][0]) + (acc[2][0] + acc[3][0]);
        float s1 = (acc[0][1] + acc[1][1]) + (acc[2][1] + acc[3][1]);
        float s2 = (acc[0][2] + acc[1][2]) + (acc[2][2] + acc[3][2]);
        float s3 = (acc[0][3] + acc[1][3]) + (acc[2][3] + acc[3][3]);

        // ---- epilogue: x_new = 0.8*x_post + 0.2*acc + drive; store x_seq ----
        x0 = (1.f - ALPHA_N) * xp0 + ALPHA_N * s0 + d0.x;
        x1 = (1.f - ALPHA_N) * xp1 + ALPHA_N * s1 + d0.y;
        x2 = (1.f - ALPHA_N) * xp2 + ALPHA_N * s2 + d1.x;
        x3 = (1.f - ALPHA_N) * xp3 + ALPHA_N * s3 + d1.y;
        *reinterpret_cast<float2*>(&out_x[((size_t)br0 * T_STEPS + ts) * NH + hb]) = make_float2(x0, x1);
        *reinterpret_cast<float2*>(&out_x[((size_t)br1 * T_STEPS + ts) * NH + hb]) = make_float2(x2, x3);
    }
}

// ---------------- y = relu(x) @ w_out_eff + b_out (R3 version) -------------
__global__ void __launch_bounds__(256) y_kernel(const float* __restrict__ out_x,
                                                const float* __restrict__ b_out)
{
    __shared__ float wsh[NH * NOUT];
    for (int i = threadIdx.x; i < NH * NOUT; i += 256) wsh[i] = g_wout[i];
    __syncthreads();

    int w = threadIdx.x >> 5, lane = threadIdx.x & 31;
    int row = blockIdx.x * 8 + w;           // t*256 + b
    int t = row >> 8;
    int b = row & 255;
    const float* xr = out_x + ((size_t)b * T_STEPS + t) * NH;

    float a0 = 0.f, a1 = 0.f, a2 = 0.f;
    #pragma unroll 4
    for (int h = lane; h < NH; h += 32) {
        float r = fmaxf(xr[h], 0.f);
        a0 += r * wsh[h * 3 + 0];
        a1 += r * wsh[h * 3 + 1];
        a2 += r * wsh[h * 3 + 2];
    }
    #pragma unroll
    for (int off = 16; off > 0; off >>= 1) {
        a0 += __shfl_xor_sync(0xffffffffu, a0, off);
        a1 += __shfl_xor_sync(0xffffffffu, a1, off);
        a2 += __shfl_xor_sync(0xffffffffu, a2, off);
    }
    if (lane == 0) {
        size_t base = ((size_t)t * BATCH + b) * NOUT;
        g_yraw[base + 0] = a0 + b_out[0];
        g_yraw[base + 1] = a1 + b_out[1];
        g_yraw[base + 2] = a2 + b_out[2];
    }
}

// ---------------- softmax over batch axis ----------------------------------
__global__ void __launch_bounds__(256) softmax_kernel(float* __restrict__ out_y)
{
    __shared__ float red[256];
    int t = blockIdx.x;
    int b = threadIdx.x;
    float v[NOUT], e[NOUT];
    #pragma unroll
    for (int o = 0; o < NOUT; o++)
        v[o] = g_yraw[((size_t)t * BATCH + b) * NOUT + o];

    #pragma unroll
    for (int o = 0; o < NOUT; o++) {
        red[b] = v[o];
        __syncthreads();
        for (int s = 128; s > 0; s >>= 1) {
            if (b < s) red[b] = fmaxf(red[b], red[b + s]);
            __syncthreads();
        }
        float mx = red[0];
        __syncthreads();
        e[o] = expf(v[o] - mx);
        red[b] = e[o];
        __syncthreads();
        for (int s = 128; s > 0; s >>= 1) {
            if (b < s) red[b] += red[b + s];
            __syncthreads();
        }
        float sm = red[0];
        __syncthreads();
        out_y[((size_t)b * T_STEPS + t) * NOUT + o] = e[o] / sm;
    }
}

// ---------------- launch ----------------------------------------------------
extern "C" void kernel_launch(void* const* d_in, const int* in_sizes, int n_in,
                              void* d_out, int out_size)
{
    const float* input_data = (const float*)d_in[0];
    const float* noise      = (const float*)d_in[1];
    const float* x_init     = (const float*)d_in[2];
    const float* syn_x_init = (const float*)d_in[3];
    const float* syn_u_init = (const float*)d_in[4];
    const float* w_in       = (const float*)d_in[5];
    const float* w_in_mask  = (const float*)d_in[6];
    const float* w_rnn_base = (const float*)d_in[7];
    const float* conn_mask  = (const float*)d_in[8];
    const float* ei_matrix  = (const float*)d_in[9];
    const float* b_rnn      = (const float*)d_in[10];
    const float* w_out      = (const float*)d_in[11];
    const float* w_out_mask = (const float*)d_in[12];
    const float* b_out      = (const float*)d_in[13];
    const float* a_std      = (const float*)d_in[14];
    const float* a_stf      = (const float*)d_in[15];
    const float* Uv         = (const float*)d_in[16];
    const float* dynv       = (const float*)d_in[17];

    float* out   = (float*)d_out;
    float* out_y = out;
    float* out_x = out + Y_SIZE;

    prep_kernel<<<148, 256>>>(w_in, w_in_mask, w_rnn_base, conn_mask, ei_matrix,
                              w_out, w_out_mask);
    dim3 dgrid(76800 / 64, NH / 64);
    drive_gemm<<<dgrid, 256>>>(input_data, noise, b_rnn);
    step_kernel<<<128, 256>>>(x_init, syn_x_init, syn_u_init,
                              a_std, a_stf, Uv, dynv, out_x);
    y_kernel<<<76800 / 8, 256>>>(out_x, b_out);
    softmax_kernel<<<T_STEPS, 256>>>(out_y);
}

// round 11
// speedup vs baseline: 1.1366x; 1.1366x over previous
#include <cuda_runtime.h>
#include <cuda_fp16.h>
#include <cstdint>

#define T_STEPS 300
#define BATCH   256
#define NIN     128
#define NH      512
#define NOUT    3
#define DTSEC   0.01f
#define ALPHA_N 0.2f

#define Y_SIZE (BATCH * T_STEPS * NOUT)
#define TS_PAD 304

// ---------------- device scratch (static, allocation-free) ----------------
__device__ float     g_drive[(size_t)T_STEPS * BATCH * NH];   // 157 MB
__device__ uint32_t  g_wrnnp[(NH / 2) * NH];                  // packed half2 (k-pair x h)
__device__ uint32_t  g_winp[(NIN / 2) * NH];
__device__ float     g_wout[NH * NOUT];
__device__ __half    g_rpost[2 * BATCH * NH];                 // double-buffered activations
__device__ float     g_yraw[(size_t)T_STEPS * BATCH * NOUT];
__device__ unsigned  g_flag[16 * 8 * TS_PAD];                 // per (group, slice, step)

// ---------------- prep -----------------------------------------------------
__global__ void prep_kernel(const float* __restrict__ w_in, const float* __restrict__ w_in_mask,
                            const float* __restrict__ w_rnn_base, const float* __restrict__ conn,
                            const float* __restrict__ ei, const float* __restrict__ w_out,
                            const float* __restrict__ w_out_mask)
{
    int tid = blockIdx.x * blockDim.x + threadIdx.x;
    int nth = gridDim.x * blockDim.x;

    for (int i = tid; i < (NH / 2) * NH; i += nth) {
        int p = i >> 9, h = i & (NH - 1);
        int k0 = 2 * p, k1 = 2 * p + 1;
        float s0 = ei[k0 * NH + k0];
        float s1 = ei[k1 * NH + k1];
        float v0 = fmaxf(w_rnn_base[k0 * NH + h] * conn[k0 * NH + h], 0.f) * s0;
        float v1 = fmaxf(w_rnn_base[k1 * NH + h] * conn[k1 * NH + h], 0.f) * s1;
        __half2 hv = __floats2half2_rn(v0, v1);
        g_wrnnp[i] = *reinterpret_cast<uint32_t*>(&hv);
    }
    for (int i = tid; i < (NIN / 2) * NH; i += nth) {
        int p = i >> 9, h = i & (NH - 1);
        float v0 = w_in[(2 * p) * NH + h] * w_in_mask[(2 * p) * NH + h];
        float v1 = w_in[(2 * p + 1) * NH + h] * w_in_mask[(2 * p + 1) * NH + h];
        __half2 hv = __floats2half2_rn(v0, v1);
        g_winp[i] = *reinterpret_cast<uint32_t*>(&hv);
    }
    for (int i = tid; i < NH * NOUT; i += nth)
        g_wout[i] = fmaxf(w_out[i] * w_out_mask[i], 0.f);
    for (int i = tid; i < 16 * 8 * TS_PAD; i += nth)
        g_flag[i] = 0u;
}

// ---------------- drive GEMM: drive = 0.2*(inp@w_in_eff + b_rnn) + noise ---
__global__ void __launch_bounds__(256) drive_gemm(const float* __restrict__ inp,
                                                  const float* __restrict__ noise,
                                                  const float* __restrict__ b_rnn)
{
    __shared__ __half   a_s[64 * 136];
    __shared__ uint32_t b_s[64 * 68];

    int row0 = blockIdx.x * 64;
    int n0   = blockIdx.y * 64;
    int tid  = threadIdx.x;

    #pragma unroll
    for (int j = 0; j < 32; j++) {
        int idx = tid + j * 256;
        int i = idx >> 7, k = idx & 127;
        a_s[i * 136 + k] = __float2half_rn(inp[(size_t)(row0 + i) * NIN + k]);
    }
    #pragma unroll
    for (int j = 0; j < 16; j++) {
        int idx = tid + j * 256;
        int p = idx >> 6, c = idx & 63;
        b_s[p * 68 + c] = g_winp[p * NH + n0 + c];
    }
    __syncthreads();

    int w = tid >> 5, lane = tid & 31;
    int g = lane >> 2, t = lane & 3;
    int m0 = (w & 3) * 16;
    int nw = (w >> 2) * 32;

    float acc[4][4] = {};
    #pragma unroll
    for (int kk = 0; kk < 8; kk++) {
        int k0 = kk * 16;
        uint32_t a0 = *reinterpret_cast<const uint32_t*>(&a_s[(m0 + g) * 136 + k0 + 2 * t]);
        uint32_t a1 = *reinterpret_cast<const uint32_t*>(&a_s[(m0 + g + 8) * 136 + k0 + 2 * t]);
        uint32_t a2 = *reinterpret_cast<const uint32_t*>(&a_s[(m0 + g) * 136 + k0 + 8 + 2 * t]);
        uint32_t a3 = *reinterpret_cast<const uint32_t*>(&a_s[(m0 + g + 8) * 136 + k0 + 8 + 2 * t]);
        #pragma unroll
        for (int s = 0; s < 4; s++) {
            int col = nw + 8 * s + g;
            uint32_t b0 = b_s[(kk * 8 + t) * 68 + col];
            uint32_t b1 = b_s[(kk * 8 + t + 4) * 68 + col];
            asm volatile("mma.sync.aligned.m16n8k16.row.col.f32.f16.f16.f32 "
                         "{%0,%1,%2,%3}, {%4,%5,%6,%7}, {%8,%9}, {%0,%1,%2,%3};"
                         : "+f"(acc[s][0]), "+f"(acc[s][1]), "+f"(acc[s][2]), "+f"(acc[s][3])
                         : "r"(a0), "r"(a1), "r"(a2), "r"(a3), "r"(b0), "r"(b1));
        }
    }

    #pragma unroll
    for (int s = 0; s < 4; s++) {
        int gc  = n0 + nw + 8 * s + 2 * t;
        float br0 = b_rnn[gc], br1 = b_rnn[gc + 1];
        int r0 = row0 + m0 + g;
        int r1 = r0 + 8;
        float2 nz0 = *reinterpret_cast<const float2*>(&noise[(size_t)r0 * NH + gc]);
        float2 nz1 = *reinterpret_cast<const float2*>(&noise[(size_t)r1 * NH + gc]);
        float2 d0, d1;
        d0.x = ALPHA_N * (acc[s][0] + br0) + nz0.x;
        d0.y = ALPHA_N * (acc[s][1] + br1) + nz0.y;
        d1.x = ALPHA_N * (acc[s][2] + br0) + nz1.x;
        d1.y = ALPHA_N * (acc[s][3] + br1) + nz1.y;
        *reinterpret_cast<float2*>(&g_drive[(size_t)r0 * NH + gc]) = d0;
        *reinterpret_cast<float2*>(&g_drive[(size_t)r1 * NH + gc]) = d1;
    }
}

// ---------------- persistent step kernel -----------------------------------
// 128 CTAs = 16 b-groups x 8 h-slices. K-split per warp: warp w computes
// partial C over k-range [64w, 64w+64) (= slice w, whose flag it polls),
// loading A-fragments DIRECTLY from L2 into registers (no smem staging, no
// ldmatrix). Flat smem reduction combines the 8 k-partials.
__global__ void __launch_bounds__(256, 1) step_kernel(
    const float* __restrict__ x_init, const float* __restrict__ sx_init,
    const float* __restrict__ su_init,
    const float* __restrict__ a_std, const float* __restrict__ a_stf,
    const float* __restrict__ Uv, const float* __restrict__ dynv,
    float* __restrict__ out_x)
{
    __shared__ float red[8][16][72];     // per-warp partial C, padded rows

    int cta   = blockIdx.x;
    int grp   = cta >> 3;
    int slice = cta & 7;
    int b0 = grp * 16;
    int h0 = slice * 64;
    int tid = threadIdx.x;
    int w = tid >> 5, lane = tid & 31;
    int g = lane >> 2, t = lane & 3;

    // ---- persistent B fragments: warp w's k-range x this CTA's 64 cols ----
    // global kstep K = 4w + kk; k-pair p = 32w + 8kk + t (+4 for b1)
    uint32_t breg0[32], breg1[32];
    #pragma unroll
    for (int kk = 0; kk < 4; kk++)
        #pragma unroll
        for (int j = 0; j < 8; j++) {
            int col = h0 + 8 * j + g;
            breg0[kk * 8 + j] = g_wrnnp[(size_t)(32 * w + 8 * kk + t) * NH + col];
            breg1[kk * 8 + j] = g_wrnnp[(size_t)(32 * w + 8 * kk + t + 4) * NH + col];
        }

    int hb  = h0 + 8 * w + 2 * t;
    int br0 = b0 + g, br1 = b0 + g + 8;

    float as0 = a_std[hb], as1 = a_std[hb + 1];
    float af0 = a_stf[hb], af1 = a_stf[hb + 1];
    float U0  = Uv[hb],    U1  = Uv[hb + 1];
    float dy0 = dynv[hb],  dy1 = dynv[hb + 1];

    float x0 = x_init[br0 * NH + hb],   x1 = x_init[br0 * NH + hb + 1];
    float x2 = x_init[br1 * NH + hb],   x3 = x_init[br1 * NH + hb + 1];
    float sx0 = sx_init[br0 * NH + hb], sx1 = sx_init[br0 * NH + hb + 1];
    float sx2 = sx_init[br1 * NH + hb], sx3 = sx_init[br1 * NH + hb + 1];
    float su0 = su_init[br0 * NH + hb], su1 = su_init[br0 * NH + hb + 1];
    float su2 = su_init[br1 * NH + hb], su3 = su_init[br1 * NH + hb + 1];

    __half2* rgl = reinterpret_cast<__half2*>(g_rpost);

    unsigned* my_flag   = g_flag + (grp * 8 + slice) * TS_PAD;   // producer stream
    unsigned* poll_flag = g_flag + (grp * 8 + w) * TS_PAD;       // warp w consumes slice w

    for (int ts = 0; ts < T_STEPS; ts++) {
        // ---- prefetch drive early (consumed after MMA) ----
        float2 d0 = *reinterpret_cast<const float2*>(&g_drive[((size_t)ts * BATCH + br0) * NH + hb]);
        float2 d1 = *reinterpret_cast<const float2*>(&g_drive[((size_t)ts * BATCH + br1) * NH + hb]);

        // ---- phase 1: STP update + x_post + rpost ----
        float xp0, xp1, xp2, xp3;
        {
            float r, sxn, sun;
            r = fmaxf(x0, 0.f);
            sxn = sx0 + (as0 * (1.f - sx0) - DTSEC * su0 * sx0 * r) * dy0;
            sun = su0 + (af0 * (U0 - su0) + DTSEC * U0 * (1.f - su0) * r) * dy0;
            sx0 = fminf(fmaxf(sxn, 0.f), 1.f); su0 = fminf(fmaxf(sun, 0.f), 1.f);
            xp0 = su0 * sx0 * x0;

            r = fmaxf(x1, 0.f);
            sxn = sx1 + (as1 * (1.f - sx1) - DTSEC * su1 * sx1 * r) * dy1;
            sun = su1 + (af1 * (U1 - su1) + DTSEC * U1 * (1.f - su1) * r) * dy1;
            sx1 = fminf(fmaxf(sxn, 0.f), 1.f); su1 = fminf(fmaxf(sun, 0.f), 1.f);
            xp1 = su1 * sx1 * x1;

            r = fmaxf(x2, 0.f);
            sxn = sx2 + (as0 * (1.f - sx2) - DTSEC * su2 * sx2 * r) * dy0;
            sun = su2 + (af0 * (U0 - su2) + DTSEC * U0 * (1.f - su2) * r) * dy0;
            sx2 = fminf(fmaxf(sxn, 0.f), 1.f); su2 = fminf(fmaxf(sun, 0.f), 1.f);
            xp2 = su2 * sx2 * x2;

            r = fmaxf(x3, 0.f);
            sxn = sx3 + (as1 * (1.f - sx3) - DTSEC * su3 * sx3 * r) * dy1;
            sun = su3 + (af1 * (U1 - su3) + DTSEC * U1 * (1.f - su3) * r) * dy1;
            sx3 = fminf(fmaxf(sxn, 0.f), 1.f); su3 = fminf(fmaxf(sun, 0.f), 1.f);
            xp3 = su3 * sx3 * x3;
        }
        int buf = ts & 1;
        rgl[(buf * BATCH * NH + br0 * NH + hb) >> 1] =
            __floats2half2_rn(fmaxf(xp0, 0.f), fmaxf(xp1, 0.f));
        rgl[(buf * BATCH * NH + br1 * NH + hb) >> 1] =
            __floats2half2_rn(fmaxf(xp2, 0.f), fmaxf(xp3, 0.f));

        // ---- publish: single-writer release flag (no RMW) ----
        // This barrier also guarantees all warps finished last step's reduce
        // loads before red[] is overwritten below.
        __syncthreads();
        if (tid == 0)
            asm volatile("st.release.gpu.global.u32 [%0], %1;"
                         :: "l"(my_flag + ts), "r"(1u) : "memory");

        // ---- per-warp: wait for slice w, pull A-fragments to registers ----
        if (w != slice && lane == 0) {
            unsigned v;
            do {
                asm volatile("ld.acquire.gpu.global.u32 %0, [%1];"
                             : "=r"(v) : "l"(poll_flag + ts) : "memory");
            } while (!v);
        }
        __syncwarp();

        uint32_t af[16];
        {
            const __half* Ap = g_rpost + (size_t)buf * BATCH * NH
                               + (size_t)(b0 + g) * NH + 64 * w + 2 * t;
            #pragma unroll
            for (int kk = 0; kk < 4; kk++) {
                asm volatile("ld.global.cg.b32 %0, [%1];"
                             : "=r"(af[kk * 4 + 0]) : "l"(Ap + 16 * kk));
                asm volatile("ld.global.cg.b32 %0, [%1];"
                             : "=r"(af[kk * 4 + 1]) : "l"(Ap + 8 * NH + 16 * kk));
                asm volatile("ld.global.cg.b32 %0, [%1];"
                             : "=r"(af[kk * 4 + 2]) : "l"(Ap + 16 * kk + 8));
                asm volatile("ld.global.cg.b32 %0, [%1];"
                             : "=r"(af[kk * 4 + 3]) : "l"(Ap + 8 * NH + 16 * kk + 8));
            }
        }

        // ---- partial mma: C_w[16x64] = rpost[16, k-slice w] @ W[k-slice w, :]
        float acc[8][4] = {};
        #pragma unroll
        for (int kk = 0; kk < 4; kk++)
            #pragma unroll
            for (int j = 0; j < 8; j++)
                asm volatile("mma.sync.aligned.m16n8k16.row.col.f32.f16.f16.f32 "
                             "{%0,%1,%2,%3}, {%4,%5,%6,%7}, {%8,%9}, {%0,%1,%2,%3};"
                             : "+f"(acc[j][0]), "+f"(acc[j][1]), "+f"(acc[j][2]), "+f"(acc[j][3])
                             : "r"(af[kk * 4 + 0]), "r"(af[kk * 4 + 1]),
                               "r"(af[kk * 4 + 2]), "r"(af[kk * 4 + 3]),
                               "r"(breg0[kk * 8 + j]), "r"(breg1[kk * 8 + j]));

        // ---- store partials to smem ----
        #pragma unroll
        for (int j = 0; j < 8; j++) {
            *reinterpret_cast<float2*>(&red[w][g][8 * j + 2 * t]) =
                make_float2(acc[j][0], acc[j][1]);
            *reinterpret_cast<float2*>(&red[w][g + 8][8 * j + 2 * t]) =
                make_float2(acc[j][2], acc[j][3]);
        }
        __syncthreads();

        // ---- reduce: each thread sums its 4 owned outputs over 8 partials ----
        float s0 = 0.f, s1 = 0.f, s2 = 0.f, s3 = 0.f;
        #pragma unroll
        for (int u = 0; u < 8; u++) {
            float2 p = *reinterpret_cast<const float2*>(&red[u][g][8 * w + 2 * t]);
            float2 q = *reinterpret_cast<const float2*>(&red[u][g + 8][8 * w + 2 * t]);
            s0 += p.x; s1 += p.y; s2 += q.x; s3 += q.y;
        }

        // ---- epilogue: x_new = 0.8*x_post + 0.2*acc + drive; store x_seq ----
        x0 = (1.f - ALPHA_N) * xp0 + ALPHA_N * s0 + d0.x;
        x1 = (1.f - ALPHA_N) * xp1 + ALPHA_N * s1 + d0.y;
        x2 = (1.f - ALPHA_N) * xp2 + ALPHA_N * s2 + d1.x;
        x3 = (1.f - ALPHA_N) * xp3 + ALPHA_N * s3 + d1.y;
        *reinterpret_cast<float2*>(&out_x[((size_t)br0 * T_STEPS + ts) * NH + hb]) = make_float2(x0, x1);
        *reinterpret_cast<float2*>(&out_x[((size_t)br1 * T_STEPS + ts) * NH + hb]) = make_float2(x2, x3);
    }
}

// ---------------- y = relu(x) @ w_out_eff + b_out (R3 version) -------------
__global__ void __launch_bounds__(256) y_kernel(const float* __restrict__ out_x,
                                                const float* __restrict__ b_out)
{
    __shared__ float wsh[NH * NOUT];
    for (int i = threadIdx.x; i < NH * NOUT; i += 256) wsh[i] = g_wout[i];
    __syncthreads();

    int w = threadIdx.x >> 5, lane = threadIdx.x & 31;
    int row = blockIdx.x * 8 + w;           // t*256 + b
    int t = row >> 8;
    int b = row & 255;
    const float* xr = out_x + ((size_t)b * T_STEPS + t) * NH;

    float a0 = 0.f, a1 = 0.f, a2 = 0.f;
    #pragma unroll 4
    for (int h = lane; h < NH; h += 32) {
        float r = fmaxf(xr[h], 0.f);
        a0 += r * wsh[h * 3 + 0];
        a1 += r * wsh[h * 3 + 1];
        a2 += r * wsh[h * 3 + 2];
    }
    #pragma unroll
    for (int off = 16; off > 0; off >>= 1) {
        a0 += __shfl_xor_sync(0xffffffffu, a0, off);
        a1 += __shfl_xor_sync(0xffffffffu, a1, off);
        a2 += __shfl_xor_sync(0xffffffffu, a2, off);
    }
    if (lane == 0) {
        size_t base = ((size_t)t * BATCH + b) * NOUT;
        g_yraw[base + 0] = a0 + b_out[0];
        g_yraw[base + 1] = a1 + b_out[1];
        g_yraw[base + 2] = a2 + b_out[2];
    }
}

// ---------------- softmax over batch axis ----------------------------------
__global__ void __launch_bounds__(256) softmax_kernel(float* __restrict__ out_y)
{
    __shared__ float red[256];
    int t = blockIdx.x;
    int b = threadIdx.x;
    float v[NOUT], e[NOUT];
    #pragma unroll
    for (int o = 0; o < NOUT; o++)
        v[o] = g_yraw[((size_t)t * BATCH + b) * NOUT + o];

    #pragma unroll
    for (int o = 0; o < NOUT; o++) {
        red[b] = v[o];
        __syncthreads();
        for (int s = 128; s > 0; s >>= 1) {
            if (b < s) red[b] = fmaxf(red[b], red[b + s]);
            __syncthreads();
        }
        float mx = red[0];
        __syncthreads();
        e[o] = expf(v[o] - mx);
        red[b] = e[o];
        __syncthreads();
        for (int s = 128; s > 0; s >>= 1) {
            if (b < s) red[b] += red[b + s];
            __syncthreads();
        }
        float sm = red[0];
        __syncthreads();
        out_y[((size_t)b * T_STEPS + t) * NOUT + o] = e[o] / sm;
    }
}

// ---------------- launch ----------------------------------------------------
extern "C" void kernel_launch(void* const* d_in, const int* in_sizes, int n_in,
                              void* d_out, int out_size)
{
    const float* input_data = (const float*)d_in[0];
    const float* noise      = (const float*)d_in[1];
    const float* x_init     = (const float*)d_in[2];
    const float* syn_x_init = (const float*)d_in[3];
    const float* syn_u_init = (const float*)d_in[4];
    const float* w_in       = (const float*)d_in[5];
    const float* w_in_mask  = (const float*)d_in[6];
    const float* w_rnn_base = (const float*)d_in[7];
    const float* conn_mask  = (const float*)d_in[8];
    const float* ei_matrix  = (const float*)d_in[9];
    const float* b_rnn      = (const float*)d_in[10];
    const float* w_out      = (const float*)d_in[11];
    const float* w_out_mask = (const float*)d_in[12];
    const float* b_out      = (const float*)d_in[13];
    const float* a_std      = (const float*)d_in[14];
    const float* a_stf      = (const float*)d_in[15];
    const float* Uv         = (const float*)d_in[16];
    const float* dynv       = (const float*)d_in[17];

    float* out   = (float*)d_out;
    float* out_y = out;
    float* out_x = out + Y_SIZE;

    prep_kernel<<<148, 256>>>(w_in, w_in_mask, w_rnn_base, conn_mask, ei_matrix,
                              w_out, w_out_mask);
    dim3 dgrid(76800 / 64, NH / 64);
    drive_gemm<<<dgrid, 256>>>(input_data, noise, b_rnn);
    step_kernel<<<128, 256>>>(x_init, syn_x_init, syn_u_init,
                              a_std, a_stf, Uv, dynv, out_x);
    y_kernel<<<76800 / 8, 256>>>(out_x, b_out);
    softmax_kernel<<<T_STEPS, 256>>>(out_y);
}